// round 12
// baseline (speedup 1.0000x reference)
#include <cuda_runtime.h>
#include <cuda_bf16.h>
#include <cstdint>

#define BATCH 4
#define NQ 20
#define DIM (1u << NQ)

__device__ float2 g_state[BATCH * DIM];                 // 32 MB (kA -> kB)
__device__ __nv_bfloat162 g_Gh[(size_t)BATCH * 1024 * 1024];  // 16 MB: bf16-hi of G (K=2048)
__device__ __nv_bfloat162 g_Gl[(size_t)BATCH * 1024 * 1024];  // 16 MB: residual lo

__device__ float2 d_F[19][16];   // fused 4x4 chain gates (row-major, i=2*s_q+s_{q+1})

// ---------------------------------------------------------------------------
// helpers
// ---------------------------------------------------------------------------
typedef unsigned long long u64;
__device__ __forceinline__ uint32_t smem_u32(const void* p) {
    uint32_t a;
    asm("{ .reg .u64 t; cvta.to.shared.u64 t, %1; cvt.u32.u64 %0, t; }" : "=r"(a) : "l"(p));
    return a;
}
__device__ __forceinline__ void cpa16(uint32_t dst, const void* src) {
    asm volatile("cp.async.cg.shared.global [%0], [%1], 16;" :: "r"(dst), "l"(src));
}
#define CP_COMMIT() asm volatile("cp.async.commit_group;" ::: "memory")
#define CP_WAIT0()  asm volatile("cp.async.wait_group 0;" ::: "memory")
#define CP_WAIT1()  asm volatile("cp.async.wait_group 1;" ::: "memory")

#define LDM4(r, addr) \
    asm volatile("ldmatrix.sync.aligned.m8n8.x4.shared.b16 {%0,%1,%2,%3}, [%4];" \
        : "=r"((r)[0]), "=r"((r)[1]), "=r"((r)[2]), "=r"((r)[3]) : "r"(addr))

#define MMA(d, a, b0, b1) \
    asm volatile("mma.sync.aligned.m16n8k16.row.col.f32.bf16.bf16.f32 " \
        "{%0,%1,%2,%3}, {%4,%5,%6,%7}, {%8,%9}, {%0,%1,%2,%3};" \
        : "+f"((d)[0]), "+f"((d)[1]), "+f"((d)[2]), "+f"((d)[3]) \
        : "r"((a)[0]), "r"((a)[1]), "r"((a)[2]), "r"((a)[3]), "r"(b0), "r"(b1))

// packed f32x2 ops (sm_100 PTX)
__device__ __forceinline__ u64 pk2(float x, float y) {
    u64 r; asm("mov.b64 %0, {%1, %2};" : "=l"(r) : "f"(x), "f"(y)); return r;
}
__device__ __forceinline__ void up2(u64 v, float& x, float& y) {
    asm("mov.b64 {%0, %1}, %2;" : "=f"(x), "=f"(y) : "l"(v));
}
__device__ __forceinline__ u64 fma2(u64 a, u64 b, u64 c) {
    u64 d; asm("fma.rn.f32x2 %0, %1, %2, %3;" : "=l"(d) : "l"(a), "l"(b), "l"(c)); return d;
}
__device__ __forceinline__ u64 mul2(u64 a, u64 b) {
    u64 d; asm("mul.rn.f32x2 %0, %1, %2;" : "=l"(d) : "l"(a), "l"(b)); return d;
}

// ---------------------------------------------------------------------------
// Gate precompute: fuse ALL singles into the 19 chain gates (fp64).
//   F(q,q+1) = (U2(q) (x) Q) * C(q,q+1) * (R (x) U1(q+1))
//   R = U1(0) for q==0 else I ;  Q = U2(19) for q==18 else I
// ---------------------------------------------------------------------------
struct cd { double re, im; };
__device__ __forceinline__ cd cmuld(cd a, cd b) {
    return {a.re * b.re - a.im * b.im, a.re * b.im + a.im * b.re};
}
__device__ __forceinline__ cd caddd(cd a, cd b) { return {a.re + b.re, a.im + b.im}; }
__device__ void mm2(const cd* A, const cd* B, cd* C) {
    C[0] = caddd(cmuld(A[0], B[0]), cmuld(A[1], B[2]));
    C[1] = caddd(cmuld(A[0], B[1]), cmuld(A[1], B[3]));
    C[2] = caddd(cmuld(A[2], B[0]), cmuld(A[3], B[2]));
    C[3] = caddd(cmuld(A[2], B[1]), cmuld(A[3], B[3]));
}
__device__ void mm4(const cd* A, const cd* B, cd* C) {
    for (int i = 0; i < 4; i++)
        for (int j = 0; j < 4; j++) {
            cd s = {0, 0};
            for (int k = 0; k < 4; k++) s = caddd(s, cmuld(A[i * 4 + k], B[k * 4 + j]));
            C[i * 4 + j] = s;
        }
}
__device__ void kron2(const cd* A, const cd* B, cd* K) {
    for (int i0 = 0; i0 < 2; i0++)
        for (int i1 = 0; i1 < 2; i1++)
            for (int j0 = 0; j0 < 2; j0++)
                for (int j1 = 0; j1 < 2; j1++)
                    K[(2 * i0 + i1) * 4 + (2 * j0 + j1)] =
                        cmuld(A[i0 * 2 + j0], B[i1 * 2 + j1]);
}

__global__ void kprep(const float* __restrict__ w) {
    __shared__ double sU[2][20][4][2];  // [layer][q][elem][re/im]
    int t = threadIdx.x;
    const double WM = 0.6324555320336759;  // sqrt(2)/sqrt(5)
    if (t < 40) {
        int q = t % 20;
        int layer = t < 20 ? 0 : 1;
        int base = layer == 0 ? 3 * q : (117 + 3 * q);
        double ax = (double)w[base]     * WM * 0.5;
        double ay = (double)w[base + 1] * WM * 0.5;
        double az = (double)w[base + 2] * WM * 0.5;
        double cx = cos(ax), sx = sin(ax);
        double cy = cos(ay), sy = sin(ay);
        double cz = cos(az), sz = sin(az);
        cd RX[4] = {{cx, 0}, {0, -sx}, {0, -sx}, {cx, 0}};
        cd RY[4] = {{cy, 0}, {-sy, 0}, {sy, 0}, {cy, 0}};
        cd RYX[4]; mm2(RY, RX, RYX);
        cd z0 = {cz, -sz}, z1 = {cz, sz};
        cd U[4] = {cmuld(z0, RYX[0]), cmuld(z0, RYX[1]),
                   cmuld(z1, RYX[2]), cmuld(z1, RYX[3])};
        for (int i = 0; i < 4; i++) { sU[layer][q][i][0] = U[i].re; sU[layer][q][i][1] = U[i].im; }
    }
    __syncthreads();
    if (t < 19) {
        int q = t;
        int base = 60 + 3 * q;
        double ax = (double)w[base]     * WM * 0.5;
        double ay = (double)w[base + 1] * WM * 0.5;
        double az = (double)w[base + 2] * WM * 0.5;
        double cx = cos(ax), sx = sin(ax);
        double cy = cos(ay), sy = sin(ay);
        double cz = cos(az), sz = sin(az);
        cd RXXb[4] = {{cx, 0}, {0, -sx}, {0, -sx}, {cx, 0}};
        cd RYY0[4] = {{cy, 0}, {0,  sy}, {0,  sy}, {cy, 0}};
        cd RYY1[4] = {{cy, 0}, {0, -sy}, {0, -sy}, {cy, 0}};
        cd M0[4]; mm2(RYY0, RXXb, M0);
        cd M1[4]; mm2(RYY1, RXXb, M1);
        cd p0 = {cz, -sz}, p1 = {cz, sz};
        cd g00[4], g01[4];
        for (int i = 0; i < 4; i++) { g00[i] = cmuld(p0, M0[i]); g01[i] = cmuld(p1, M1[i]); }
        cd C[16];
        for (int i = 0; i < 16; i++) C[i] = {0, 0};
        C[0 * 4 + 0] = g00[0]; C[0 * 4 + 3] = g00[1];
        C[3 * 4 + 0] = g00[2]; C[3 * 4 + 3] = g00[3];
        C[1 * 4 + 1] = g01[0]; C[1 * 4 + 2] = g01[1];
        C[2 * 4 + 1] = g01[2]; C[2 * 4 + 2] = g01[3];
        cd I2[4] = {{1, 0}, {0, 0}, {0, 0}, {1, 0}};
        cd R[4], S[4], P[4], Q[4];
        for (int i = 0; i < 4; i++) {
            R[i] = (q == 0)  ? cd{sU[0][0][i][0],  sU[0][0][i][1]}  : I2[i];
            S[i] = cd{sU[0][q + 1][i][0], sU[0][q + 1][i][1]};
            P[i] = cd{sU[1][q][i][0],     sU[1][q][i][1]};
            Q[i] = (q == 18) ? cd{sU[1][19][i][0], sU[1][19][i][1]} : I2[i];
        }
        cd PRE[16], POST[16], T[16], F[16];
        kron2(R, S, PRE);
        kron2(P, Q, POST);
        mm4(C, PRE, T);
        mm4(POST, T, F);
        for (int i = 0; i < 16; i++)
            d_F[q][i] = make_float2((float)F[i].re, (float)F[i].im);
    }
}

// ---------------------------------------------------------------------------
// Fused 4x4 gate sweep, packed f32x2 math.
// Gate g kept in natural (re,im) packing (u64). Two SIMD partial sums:
//   accA = sum_j g_j * (vr_j, vr_j)  -> (sum gr*vr, sum gi*vr)
//   accB = sum_j g_j * (vi_j, vi_j)  -> (sum gr*vi, sum gi*vi)
//   out  = (accA.lo - accB.hi, accA.hi + accB.lo)
// ---------------------------------------------------------------------------
__device__ __forceinline__ void apply4(float2* sv, const float2* __restrict__ G,
                                       int lb, int tid) {
    u64 g[16];
    const u64* gp = (const u64*)G;
    #pragma unroll
    for (int i = 0; i < 16; i++) g[i] = gp[i];
    #pragma unroll
    for (int grp = tid; grp < 1024; grp += 256) {
        int low  = grp & ((1 << lb) - 1);
        int base = ((grp >> lb) << (lb + 2)) | low;
        int i1 = base | (1 << lb);
        int i2 = base | (2 << lb);
        int i3 = base | (3 << lb);
        float2 v0 = sv[base], v1 = sv[i1], v2 = sv[i2], v3 = sv[i3];
        u64 vr[4] = {pk2(v0.x, v0.x), pk2(v1.x, v1.x), pk2(v2.x, v2.x), pk2(v3.x, v3.x)};
        u64 vi[4] = {pk2(v0.y, v0.y), pk2(v1.y, v1.y), pk2(v2.y, v2.y), pk2(v3.y, v3.y)};
        float2 o[4];
        #pragma unroll
        for (int r = 0; r < 4; r++) {
            u64 aA = mul2(g[4 * r], vr[0]);
            u64 aB = mul2(g[4 * r], vi[0]);
            #pragma unroll
            for (int j = 1; j < 4; j++) {
                aA = fma2(g[4 * r + j], vr[j], aA);
                aB = fma2(g[4 * r + j], vi[j], aB);
            }
            float a0, a1, b0, b1;
            up2(aA, a0, a1);
            up2(aB, b0, b1);
            o[r] = make_float2(a0 - b1, a1 + b0);
        }
        sv[base] = o[0]; sv[i1] = o[1]; sv[i2] = o[2]; sv[i3] = o[3];
    }
}

// Kernel A: tile = bits {0,1} U {10..19}. Fused chains q=0..8
__global__ void __launch_bounds__(256) kA(const float* __restrict__ x) {
    __shared__ float2 sv[4096];
    int tid = threadIdx.x;
    int b   = blockIdx.x >> 8;
    int mid = blockIdx.x & 255;
    const float* xb = x + ((size_t)b << NQ);
    float2* gb = g_state + ((size_t)b << NQ);
    for (int s = tid; s < 4096; s += 256) {
        int H = s >> 2, c2 = s & 3;
        sv[s] = make_float2(xb[(H << 10) | (mid << 2) | c2], 0.0f);
    }
    __syncthreads();
    #pragma unroll
    for (int q = 0; q < 9; q++) { apply4(sv, d_F[q], 10 - q, tid); __syncthreads(); }
    for (int s = tid; s < 4096; s += 256) {
        int H = s >> 2, c2 = s & 3;
        gb[(H << 10) | (mid << 2) | c2] = sv[s];
    }
}

// Kernel B: tile = low bits 0..11. Fused chains q=9..18.
// Epilogue: bf16 hi/lo split of G, K-major (K=2048).
__global__ void __launch_bounds__(256) kB() {
    __shared__ float2 sv[4096];
    int tid = threadIdx.x;
    int b   = blockIdx.x >> 8;
    int hib = blockIdx.x & 255;  // t bits 2..9
    float2* gb = g_state + ((size_t)b << NQ) + ((size_t)hib << 12);

    for (int s = tid; s < 4096; s += 256) sv[s] = gb[s];
    __syncthreads();
    #pragma unroll
    for (int q = 9; q < 19; q++) { apply4(sv, d_F[q], 18 - q, tid); __syncthreads(); }

    size_t mb = (size_t)b * (1024 * 1024);  // bf162 units
    int k2 = hib * 4;
    for (int a = tid; a < 1024; a += 256) {
        __nv_bfloat162 gh[4], gl[4];
        #pragma unroll
        for (int t2 = 0; t2 < 4; t2++) {
            float2 v = sv[(t2 << 10) | a];
            __nv_bfloat162 h = __floats2bfloat162_rn(v.x, v.y);
            float hr = __bfloat162float(__low2bfloat16(h));
            float hi = __bfloat162float(__high2bfloat16(h));
            gh[t2] = h;
            gl[t2] = __floats2bfloat162_rn(v.x - hr, v.y - hi);
        }
        size_t off = mb + (size_t)a * 1024 + k2;
        *(uint4*)&g_Gh[off] = *(uint4*)gh;
        *(uint4*)&g_Gl[off] = *(uint4*)gl;
    }
}

// ---------------------------------------------------------------------------
// Kernel C: rdm via bf16 mma.sync, 3-term hi/lo split.  (UNCHANGED from the
// proven 193us round-11 version: TPITCH 80, K-chunk 32, 3-stage ring.)
//   Re = G_a G_c^T ; Im = H_a G_c^T, H derived in-register:
//   H reg = halfword_swap(G reg) ^ 0x80000000
// ---------------------------------------------------------------------------
#define TPITCH 80                       // 64B data + 16B pad: conflict-free ldmatrix
#define TILE_SM (128 * TPITCH)          // 10240 B
#define STAGE_SM (4 * TILE_SM)          // Gh_a, Gl_a, Gh_c, Gl_c = 40960 B
#define NSTAGE 3
#define SMEM_KC (NSTAGE * STAGE_SM)     // 122880 B

__device__ __forceinline__ void kc_load(uint32_t sb, int buf,
                                        const __nv_bfloat16* const* srcs,
                                        int kc, int tid) {
    int row = tid >> 2, c = tid & 3;
    uint32_t dst = sb + buf * STAGE_SM + row * TPITCH + c * 16;
    #pragma unroll
    for (int t = 0; t < 4; t++)
        cpa16(dst + t * TILE_SM, srcs[t] + (size_t)row * 2048 + kc + c * 8);
}

__global__ void __launch_bounds__(512, 1) kC(float2* __restrict__ out) {
    extern __shared__ char smc[];
    uint32_t sb = smem_u32(smc);
    int tid = threadIdx.x, lane = tid & 31, wid = tid >> 5;
    int wm = wid >> 2, wn = wid & 3;

    int z = blockIdx.x;
    int b = z / 36;
    int pair = z - b * 36;
    int bi = 0;
    while (pair >= 8 - bi) { pair -= 8 - bi; bi++; }
    int bj = bi + pair;
    int a0 = bi << 7, c0 = bj << 7;

    const __nv_bfloat16* Gh = (const __nv_bfloat16*)(g_Gh + (size_t)b * 1024 * 1024);
    const __nv_bfloat16* Gl = (const __nv_bfloat16*)(g_Gl + (size_t)b * 1024 * 1024);
    const __nv_bfloat16* srcs[4] = {
        Gh + (size_t)a0 * 2048, Gl + (size_t)a0 * 2048,
        Gh + (size_t)c0 * 2048, Gl + (size_t)c0 * 2048 };

    float accR[2][4][4], accI[2][4][4];
    #pragma unroll
    for (int i = 0; i < 2; i++)
        #pragma unroll
        for (int j = 0; j < 4; j++)
            #pragma unroll
            for (int k = 0; k < 4; k++) { accR[i][j][k] = 0.f; accI[i][j][k] = 0.f; }

    uint32_t loff = (uint32_t)((lane & 15) * TPITCH + (lane >> 4) * 16);

    // prefetch stages 0 and 1 (distance-2 pipeline)
    kc_load(sb, 0, srcs, 0, tid);
    CP_COMMIT();
    kc_load(sb, 1, srcs, 32, tid);
    CP_COMMIT();

    int buf = 0;
    for (int s = 0; s < 64; s++) {
        if (s < 63) CP_WAIT1(); else CP_WAIT0();  // stage s arrived (s+1 may be in flight)
        __syncthreads();  // all threads' stage-s data visible; prior consumption of
                          // buf (s+2)%3 finished -> safe to overwrite it below
        if (s + 2 < 64) {
            int nbuf = buf + 2; if (nbuf >= NSTAGE) nbuf -= NSTAGE;
            kc_load(sb, nbuf, srcs, (s + 2) * 32, tid);
            CP_COMMIT();
        }

        uint32_t st = sb + buf * STAGE_SM + loff;
        #pragma unroll
        for (int ks = 0; ks < 2; ks++) {
            uint32_t ko = (uint32_t)(ks * 32);
            uint32_t AH[2][4], AL[2][4], BH[2][4], BL[2][4];
            #pragma unroll
            for (int mt = 0; mt < 2; mt++) {
                uint32_t ra = st + (wm * 32 + mt * 16) * TPITCH + ko;
                LDM4(AH[mt], ra);
                LDM4(AL[mt], ra + TILE_SM);
            }
            #pragma unroll
            for (int p = 0; p < 2; p++) {
                uint32_t rb = st + 2 * TILE_SM + (wn * 32 + p * 16) * TPITCH + ko;
                LDM4(BH[p], rb);
                LDM4(BL[p], rb + TILE_SM);
            }
            #pragma unroll
            for (int mt = 0; mt < 2; mt++) {
                uint32_t HH[4], HL[4];
                #pragma unroll
                for (int i = 0; i < 4; i++) {
                    HH[i] = __byte_perm(AH[mt][i], AH[mt][i], 0x1032) ^ 0x80000000u;
                    HL[i] = __byte_perm(AL[mt][i], AL[mt][i], 0x1032) ^ 0x80000000u;
                }
                #pragma unroll
                for (int nt = 0; nt < 4; nt++) {
                    int p = nt >> 1, q = nt & 1;
                    uint32_t b0h = BH[p][q], b1h = BH[p][q + 2];
                    uint32_t b0l = BL[p][q], b1l = BL[p][q + 2];
                    MMA(accR[mt][nt], AH[mt], b0h, b1h);
                    MMA(accR[mt][nt], AH[mt], b0l, b1l);
                    MMA(accR[mt][nt], AL[mt], b0h, b1h);
                    MMA(accI[mt][nt], HH, b0h, b1h);
                    MMA(accI[mt][nt], HH, b0l, b1l);
                    MMA(accI[mt][nt], HL, b0h, b1h);
                }
            }
        }
        if (++buf >= NSTAGE) buf = 0;
    }

    // epilogue: direct stores + conjugate-transposed mirror
    float2* ob = out + ((size_t)b << 20);
    int rg = a0 + wm * 32 + (lane >> 2);
    int cg = c0 + wn * 32 + 2 * (lane & 3);
    #pragma unroll
    for (int mt = 0; mt < 2; mt++) {
        #pragma unroll
        for (int nt = 0; nt < 4; nt++) {
            int r = rg + mt * 16;
            int c = cg + nt * 8;
            float* R = accR[mt][nt];
            float* I = accI[mt][nt];
            *(float4*)&ob[((size_t)r << 10) + c]       = make_float4(R[0], I[0], R[1], I[1]);
            *(float4*)&ob[((size_t)(r + 8) << 10) + c] = make_float4(R[2], I[2], R[3], I[3]);
            if (bi != bj) {
                ob[((size_t)c << 10) + r]           = make_float2(R[0], -I[0]);
                ob[((size_t)(c + 1) << 10) + r]     = make_float2(R[1], -I[1]);
                ob[((size_t)c << 10) + r + 8]       = make_float2(R[2], -I[2]);
                ob[((size_t)(c + 1) << 10) + r + 8] = make_float2(R[3], -I[3]);
            }
        }
    }
}

// ---------------------------------------------------------------------------
extern "C" void kernel_launch(void* const* d_in, const int* in_sizes, int n_in,
                              void* d_out, int out_size) {
    const float* x = (const float*)d_in[0];
    const float* w = (const float*)d_in[1];
    (void)in_sizes; (void)n_in; (void)out_size;

    cudaFuncSetAttribute(kC, cudaFuncAttributeMaxDynamicSharedMemorySize, SMEM_KC);

    kprep<<<1, 64>>>(w);
    kA<<<BATCH * 256, 256>>>(x);
    kB<<<BATCH * 256, 256>>>();
    kC<<<BATCH * 36, 512, SMEM_KC>>>((float2*)d_out);
}